// round 8
// baseline (speedup 1.0000x reference)
#include <cuda_runtime.h>

// Problem constants (fixed by setup_inputs)
#define BB    16
#define CIN   64
#define COUT  64
#define HH    224
#define WW    224
#define PHH   32
#define PWW   32
#define PLANE   (HH * WW)

// Conv tiling (R7 proven: CO_T=16, FFMA2)
#define CIN_T 16
#define CO_T  16
#define OH_T  8
#define CONV_BLOCKS (BB * (COUT / CO_T) * (PHH / OH_T))  // 256
#define NTHREADS 256

#define SIN_STRIDE_R 36
#define SIN_STRIDE_C (10 * SIN_STRIDE_R)

__device__ __forceinline__ unsigned long long pack2(float v) {
    unsigned long long r;
    asm("mov.b64 %0, {%1, %1};" : "=l"(r) : "f"(v));
    return r;
}
__device__ __forceinline__ void ffma2(unsigned long long& acc,
                                      unsigned long long w,
                                      unsigned long long v) {
    asm("fma.rn.f32x2 %0, %1, %2, %0;" : "+l"(acc) : "l"(w), "l"(v));
}

__global__ __launch_bounds__(NTHREADS, 4)
void inc_conv_patch_kernel(const float* __restrict__ in,      // (B,Cin,H,W)
                           const float* __restrict__ wgt,     // (Cout,Cin,3,3)
                           const float* __restrict__ bias,    // (Cout)
                           const int*   __restrict__ locs,    // (B,2) [y,x]
                           float*       __restrict__ dst)     // (B,Cout,H,W)
{
    __shared__ float s_in[CIN_T * SIN_STRIDE_C];
    __shared__ __align__(16) float s_w[CIN_T * 9 * CO_T];

    const int tid     = threadIdx.x;
    const int conv_id = blockIdx.x;
    const int b       = conv_id >> 4;
    const int rem     = conv_id & 15;
    const int co0     = (rem >> 2) * CO_T;
    const int oh0     = (rem & 3) * OH_T;

    const int y = locs[2 * b];
    const int x = locs[2 * b + 1];

    const int oh_l = tid >> 5;
    const int ow   = tid & 31;

    // 8 packed f32x2 accumulators = 16 couts
    unsigned long long acc[8];
    #pragma unroll
    for (int c = 0; c < 8; ++c) acc[c] = 0ULL;

    const int gr0 = y + oh0 - 1;
    const int gc0 = x - 1;

    for (int ci0 = 0; ci0 < CIN; ci0 += CIN_T) {
        for (int t = tid; t < CIN_T * 10 * 34; t += NTHREADS) {
            const int ci = t / (10 * 34);
            const int r  = (t / 34) % 10;
            const int c  = t % 34;
            const int gr = gr0 + r;
            const int gc = gc0 + c;
            float v = 0.0f;
            if (gr >= 0 && gc >= 0)
                v = in[((size_t)(b * CIN + ci0 + ci) * HH + gr) * WW + gc];
            s_in[ci * SIN_STRIDE_C + r * SIN_STRIDE_R + c] = v;
        }
        for (int t = tid; t < CO_T * CIN_T * 9; t += NTHREADS) {
            const int co = t / (CIN_T * 9);
            const int r2 = t % (CIN_T * 9);
            const int ci = r2 / 9;
            const int k  = r2 % 9;
            s_w[(ci * 9 + k) * CO_T + co] =
                wgt[((co0 + co) * CIN + ci0 + ci) * 9 + k];
        }
        __syncthreads();

        #pragma unroll 4
        for (int ci = 0; ci < CIN_T; ++ci) {
            const float* ibase = &s_in[ci * SIN_STRIDE_C + oh_l * SIN_STRIDE_R + ow];
            #pragma unroll
            for (int kh = 0; kh < 3; ++kh) {
                const float i0 = ibase[kh * SIN_STRIDE_R + 0];
                const float i1 = ibase[kh * SIN_STRIDE_R + 1];
                const float i2 = ibase[kh * SIN_STRIDE_R + 2];
                #pragma unroll
                for (int kw = 0; kw < 3; ++kw) {
                    const float ivs = (kw == 0) ? i0 : ((kw == 1) ? i1 : i2);
                    const unsigned long long vv = pack2(ivs);
                    const ulonglong2* wp =
                        (const ulonglong2*)&s_w[(ci * 9 + kh * 3 + kw) * CO_T];
                    const ulonglong2 wa = wp[0], wb = wp[1],
                                     wc = wp[2], wd = wp[3];
                    ffma2(acc[0], wa.x, vv);  ffma2(acc[1], wa.y, vv);
                    ffma2(acc[2], wb.x, vv);  ffma2(acc[3], wb.y, vv);
                    ffma2(acc[4], wc.x, vv);  ffma2(acc[5], wc.y, vv);
                    ffma2(acc[6], wd.x, vv);  ffma2(acc[7], wd.y, vv);
                }
            }
        }
        __syncthreads();
    }

    // store patch outputs (+bias); overwrites the memcpy'd stale values
    const int oy = y + oh0 + oh_l;
    const int ox = x + ow;
    #pragma unroll
    for (int j = 0; j < 8; ++j) {
        float lo, hi;
        asm("mov.b64 {%0, %1}, %2;" : "=f"(lo), "=f"(hi) : "l"(acc[j]));
        const int coA = co0 + 2 * j;
        dst[((size_t)(b * COUT + coA) * HH + oy) * WW + ox]     = lo + bias[coA];
        dst[((size_t)(b * COUT + coA + 1) * HH + oy) * WW + ox] = hi + bias[coA + 1];
    }
}

extern "C" void kernel_launch(void* const* d_in, const int* in_sizes, int n_in,
                              void* d_out, int out_size) {
    const float* in_tensor  = (const float*)d_in[0];
    const float* weights    = (const float*)d_in[1];
    const float* biases     = (const float*)d_in[2];
    const float* out_stale  = (const float*)d_in[3];
    const int*   locs       = (const int*)d_in[4];
    float*       out        = (float*)d_out;

    // 1) Bulk copy stale output -> dst via the vendor D2D path (capturable).
    //    Patch regions are copied too (2.5% extra) and overwritten by the conv.
    cudaMemcpyAsync(out, out_stale, (size_t)in_sizes[3] * sizeof(float),
                    cudaMemcpyDeviceToDevice);

    // 2) Conv over the 32x32 patches, same stream -> ordered after the copy.
    inc_conv_patch_kernel<<<CONV_BLOCKS, NTHREADS>>>(
        in_tensor, weights, biases, locs, out);
}